// round 11
// baseline (speedup 1.0000x reference)
#include <cuda_runtime.h>
#include <cuda_fp16.h>

// ---------------------------------------------------------------------------
//   q,k,v = x@W{q,k,v}^T + b   (d=3, heads share weights)
//   z3    = softmax(q k^T / sqrt(3)) v                    [B,S,3]
//   r0    = x + z3 @ Wc + bc          (Wc = wo_eff @ w1^T, [3,512])
//   y     = LN(r0)   -- fused into GEMM prologue, fp16 in smem
//   r     = r0 + y @ w2^T + b2        (single fp16 mma.sync term)
//   out   = LN(r)
// ---------------------------------------------------------------------------

#define BB   8
#define SS   2048
#define CC   512
#define RR   (BB*SS)          // 16384 rows
#define LN_EPS 1e-5f

// Scratch (device globals: allocation-free)
__device__ __align__(16) float  g_q [RR*3];
__device__ __align__(16) float  g_k [BB*3*SS];    // [b][d][s]
__device__ __align__(16) float  g_v [BB*3*SS];
__device__ __align__(16) float  g_z [RR*3];
__device__ __align__(16) float  g_Wc[3*CC];       // [d][c]
__device__ __align__(16) float  g_bc[CC];
__device__ __align__(16) float  g_r0[RR*CC];
// w2 in fp16, chunked layout [k/16][n][16]
__device__ __align__(16) __half g_w2h[CC*CC];

__device__ __forceinline__ float ex2f(float x)
{
    float r;
    asm("ex2.approx.ftz.f32 %0, %1;" : "=f"(r) : "f"(x));
    return r;
}

// ---------------------------------------------------------------------------
// Kernel 1 (fused prep): blocks 0..255 convert w2 -> fp16 chunked image;
// blocks 256..271 compute Wc = wo_eff @ w1^T and bc (parallelized:
// each block 32 outputs, 8 lanes split the 512-long dot).
// 256 threads per block.
// ---------------------------------------------------------------------------
__global__ void prep_all(const float* __restrict__ w2,
                         const float* __restrict__ wo, const float* __restrict__ bo,
                         const float* __restrict__ w1, const float* __restrict__ b1)
{
    if (blockIdx.x < 256) {
        int idx = blockIdx.x*256 + threadIdx.x;     // 0..65535
        float4 v = ((const float4*)w2)[idx];
        int n  = (idx*4) >> 9;
        int k  = (idx*4) & 511;
        int kc = k >> 4, ki = k & 15;
        size_t dst = (size_t)kc*(CC*16) + (size_t)n*16 + ki;
        ((__half2*)(g_w2h + dst))[0] = __halves2half2(__float2half_rn(v.x), __float2half_rn(v.y));
        ((__half2*)(g_w2h + dst))[1] = __halves2half2(__float2half_rn(v.z), __float2half_rn(v.w));
        return;
    }
    // ---- Wc/bc prep ----
    __shared__ __align__(16) float woe[CC*3];
    __shared__ __align__(16) float sbo[CC];
    int t = threadIdx.x;
    for (int j=t; j<CC; j+=256) {
        const float* row = wo + j*18;
        float s0=0.f, s1=0.f, s2=0.f;
        #pragma unroll
        for (int h=0; h<6; ++h) { s0 += row[h*3+0]; s1 += row[h*3+1]; s2 += row[h*3+2]; }
        woe[j*3+0]=s0; woe[j*3+1]=s1; woe[j*3+2]=s2; sbo[j]=bo[j];
    }
    __syncthreads();

    int to = (blockIdx.x - 256)*32 + (t >> 3);   // output channel
    int ln = t & 7;                              // 8 lanes per output
    const float* w1row = w1 + (size_t)to*CC + ln*64;
    float a0=0.f, a1=0.f, a2=0.f, ab=0.f;
    #pragma unroll 8
    for (int j=0; j<64; ++j) {
        float w = w1row[j];
        int jj = ln*64 + j;
        a0 += woe[jj*3+0]*w; a1 += woe[jj*3+1]*w; a2 += woe[jj*3+2]*w; ab += sbo[jj]*w;
    }
    #pragma unroll
    for (int o=4; o>0; o>>=1) {
        a0 += __shfl_xor_sync(0xffffffffu, a0, o);
        a1 += __shfl_xor_sync(0xffffffffu, a1, o);
        a2 += __shfl_xor_sync(0xffffffffu, a2, o);
        ab += __shfl_xor_sync(0xffffffffu, ab, o);
    }
    if (ln == 0) {
        g_Wc[0*CC+to]=a0; g_Wc[1*CC+to]=a1; g_Wc[2*CC+to]=a2;
        g_bc[to] = ab + b1[to];
    }
}

// ---------------------------------------------------------------------------
// Kernel 2: q,k,v projections. One warp per row, 8 rows/block, grid = RR/8.
// q pre-scaled by log2(e)/sqrt(3) so attention can use raw ex2.
// ---------------------------------------------------------------------------
__global__ void qkv_kernel(const float* __restrict__ x,
                           const float* __restrict__ wq, const float* __restrict__ bq,
                           const float* __restrict__ wk, const float* __restrict__ bk,
                           const float* __restrict__ wv, const float* __restrict__ bv)
{
    __shared__ __align__(16) float sw[9*CC];
    int t = threadIdx.x;
    for (int i=t; i<3*CC; i+=256) {
        sw[i]        = wq[i];
        sw[3*CC + i] = wk[i];
        sw[6*CC + i] = wv[i];
    }
    __syncthreads();

    int warp = t >> 5, lane = t & 31;
    int m = blockIdx.x*8 + warp;

    const float4* x4  = (const float4*)(x + (size_t)m*CC);
    const float4* sw4 = (const float4*)sw;

    float acc[9];
    #pragma unroll
    for (int r=0; r<9; ++r) acc[r] = 0.f;

    #pragma unroll
    for (int i=0; i<4; ++i) {
        int f = lane + 32*i;
        float4 xv = x4[f];
        #pragma unroll
        for (int r=0; r<9; ++r) {
            float4 w = sw4[r*128 + f];
            acc[r] += xv.x*w.x + xv.y*w.y + xv.z*w.z + xv.w*w.w;
        }
    }
    #pragma unroll
    for (int r=0; r<9; ++r) {
        #pragma unroll
        for (int o=16; o>0; o>>=1) acc[r] += __shfl_xor_sync(0xffffffffu, acc[r], o);
    }
    if (lane == 0) {
        int b = m >> 11, s = m & (SS-1);
        const float inv = 0.83296790143f;   // log2(e)/sqrt(3)
        #pragma unroll
        for (int d=0; d<3; ++d) {
            g_q[m*3+d]            = (acc[d]   + bq[d]) * inv;
            g_k[(b*3+d)*SS + s]   =  acc[3+d] + bk[d];
            g_v[(b*3+d)*SS + s]   =  acc[6+d] + bv[d];
        }
    }
}

// ---------------------------------------------------------------------------
// Kernel 3: attention, d=3, 32 queries/block (512 blocks). exp == ex2.
// ---------------------------------------------------------------------------
__global__ void __launch_bounds__(256, 2) attn_kernel()
{
    __shared__ __align__(16) float sKV[6][SS];    // 48 KB
    int t = threadIdx.x;
    int b  = blockIdx.x >> 6;
    int q0 = (blockIdx.x & 63) * 32;

    {   // bulk load K and V
        const float4* gk4 = (const float4*)(g_k + b*3*SS);
        const float4* gv4 = (const float4*)(g_v + b*3*SS);
        float4* s4 = (float4*)sKV;
        for (int i=t; i<3*SS/4; i+=256) { s4[i] = gk4[i]; s4[1536 + i] = gv4[i]; }
    }
    __syncthreads();

    int warp = t >> 5, lane = t & 31;
    const float4* K0 = (const float4*)sKV[0];
    const float4* K1 = (const float4*)sKV[1];
    const float4* K2 = (const float4*)sKV[2];
    const float4* V0 = (const float4*)sKV[3];
    const float4* V1 = (const float4*)sKV[4];
    const float4* V2 = (const float4*)sKV[5];

    #pragma unroll 1
    for (int p=0; p<2; ++p) {
        int m = b*SS + q0 + warp*4 + p*2;
        float qa0=g_q[m*3+0], qb0=g_q[m*3+1], qc0=g_q[m*3+2];
        float qa1=g_q[m*3+3], qb1=g_q[m*3+4], qc1=g_q[m*3+5];
        float ss0=0.f, a00=0.f, a01=0.f, a02=0.f;
        float ss1=0.f, a10=0.f, a11=0.f, a12=0.f;
        #pragma unroll 4
        for (int i=0; i<16; ++i) {
            int j = lane + 32*i;
            float4 k0 = K0[j], k1 = K1[j], k2 = K2[j];
            float4 v0 = V0[j], v1 = V1[j], v2 = V2[j];
            float e;
            e = ex2f(qa0*k0.x + qb0*k1.x + qc0*k2.x); ss0+=e; a00+=e*v0.x; a01+=e*v1.x; a02+=e*v2.x;
            e = ex2f(qa1*k0.x + qb1*k1.x + qc1*k2.x); ss1+=e; a10+=e*v0.x; a11+=e*v1.x; a12+=e*v2.x;
            e = ex2f(qa0*k0.y + qb0*k1.y + qc0*k2.y); ss0+=e; a00+=e*v0.y; a01+=e*v1.y; a02+=e*v2.y;
            e = ex2f(qa1*k0.y + qb1*k1.y + qc1*k2.y); ss1+=e; a10+=e*v0.y; a11+=e*v1.y; a12+=e*v2.y;
            e = ex2f(qa0*k0.z + qb0*k1.z + qc0*k2.z); ss0+=e; a00+=e*v0.z; a01+=e*v1.z; a02+=e*v2.z;
            e = ex2f(qa1*k0.z + qb1*k1.z + qc1*k2.z); ss1+=e; a10+=e*v0.z; a11+=e*v1.z; a12+=e*v2.z;
            e = ex2f(qa0*k0.w + qb0*k1.w + qc0*k2.w); ss0+=e; a00+=e*v0.w; a01+=e*v1.w; a02+=e*v2.w;
            e = ex2f(qa1*k0.w + qb1*k1.w + qc1*k2.w); ss1+=e; a10+=e*v0.w; a11+=e*v1.w; a12+=e*v2.w;
        }
        #pragma unroll
        for (int o=16; o>0; o>>=1) {
            ss0 += __shfl_xor_sync(0xffffffffu, ss0, o);
            a00 += __shfl_xor_sync(0xffffffffu, a00, o);
            a01 += __shfl_xor_sync(0xffffffffu, a01, o);
            a02 += __shfl_xor_sync(0xffffffffu, a02, o);
            ss1 += __shfl_xor_sync(0xffffffffu, ss1, o);
            a10 += __shfl_xor_sync(0xffffffffu, a10, o);
            a11 += __shfl_xor_sync(0xffffffffu, a11, o);
            a12 += __shfl_xor_sync(0xffffffffu, a12, o);
        }
        if (lane == 0) {
            float i0 = 1.f/ss0, i1 = 1.f/ss1;
            g_z[m*3+0] = a00*i0; g_z[m*3+1] = a01*i0; g_z[m*3+2] = a02*i0;
            g_z[m*3+3] = a10*i1; g_z[m*3+4] = a11*i1; g_z[m*3+5] = a12*i1;
        }
    }
}

// ---------------------------------------------------------------------------
// Kernel 4 (fused): r0 = x + z@Wc + bc ; y = LN(r0) -> smem fp16 ;
// r1 = y @ w2^T ; r = r0 + r1 + b2 ; out = LN(r).
// BM=64, BN=512 (full row), BK=32 (16 iterations), 512 threads.
// 3-stage cp.async pipeline for B; ONE barrier per iteration (top-of-iter
// sync doubles as data-ready + prev-buffer-consumed guard).
// ---------------------------------------------------------------------------
#define ACH  1032                 // halves per A k16-chunk (64*16 + 8 pad)
#define ASZ  (32*ACH)             // 33024 halves total for A
#define BCH  8192                 // halves per B k16-chunk in smem
#define BSTG (2*BCH)              // halves per pipeline stage (BK=32)
#define GEMM_SMEM ((ASZ + 3*BSTG)*2)   // 164352 bytes

__device__ __forceinline__ void mma_fp16(float d[4], const unsigned a[4], const unsigned b[2])
{
    asm volatile(
        "mma.sync.aligned.m16n8k16.row.col.f32.f16.f16.f32 "
        "{%0,%1,%2,%3}, {%4,%5,%6,%7}, {%8,%9}, {%0,%1,%2,%3};\n"
        : "+f"(d[0]), "+f"(d[1]), "+f"(d[2]), "+f"(d[3])
        : "r"(a[0]), "r"(a[1]), "r"(a[2]), "r"(a[3]), "r"(b[0]), "r"(b[1]));
}
__device__ __forceinline__ void cp16(void* smem, const void* gmem)
{
    unsigned sa = (unsigned)__cvta_generic_to_shared(smem);
    asm volatile("cp.async.cg.shared.global [%0], [%1], 16;\n" :: "r"(sa), "l"(gmem));
}
__device__ __forceinline__ void cpcommit() { asm volatile("cp.async.commit_group;\n" ::: "memory"); }
template<int N> __device__ __forceinline__ void cpwait() { asm volatile("cp.async.wait_group %0;\n" :: "n"(N) : "memory"); }

__global__ void __launch_bounds__(512, 1)
gemm_fused(const float* __restrict__ x,
           const float* __restrict__ gamma, const float* __restrict__ beta,
           const float* __restrict__ b2, float* __restrict__ out)
{
    extern __shared__ __half sdyn[];
    __half* Ash   = sdyn;
    __half* Bbase = sdyn + ASZ;
    __shared__ float csum[8][64], csq[8][64];

    int t = threadIdx.x;
    int w = t >> 5, lane = t & 31;
    int grp = lane >> 2, cp = lane & 3;
    int mwarp = w >> 3, nwarp = w & 7;
    int row0 = blockIdx.x * 64;

    // ---------------- prologue: r0 + LN + fp16 into Ash ---------------------
    {
        float* sWc = (float*)Bbase;            // scratch inside B region
        float* sbc = sWc + 3*CC;
        for (int i=t; i<3*CC; i+=512) sWc[i] = g_Wc[i];
        for (int i=t; i<CC;   i+=512) sbc[i] = g_bc[i];
        __syncthreads();

        #pragma unroll 1
        for (int rr=0; rr<4; ++rr) {
            int lrow = w*4 + rr;
            int m = row0 + lrow;
            float z0 = g_z[m*3+0], z1 = g_z[m*3+1], z2 = g_z[m*3+2];
            const float4* x4 = (const float4*)(x + (size_t)m*CC);
            float4* r0out = (float4*)(g_r0 + (size_t)m*CC);
            float vals[16];
            float sum = 0.f, sq = 0.f;
            #pragma unroll
            for (int i=0; i<4; ++i) {
                int f = lane + 32*i;
                float4 xv = x4[f];
                float4 w0 = ((const float4*)sWc)[f];
                float4 w1 = ((const float4*)sWc)[128+f];
                float4 w2 = ((const float4*)sWc)[256+f];
                float4 bc = ((const float4*)sbc)[f];
                float4 r;
                r.x = xv.x + z0*w0.x + z1*w1.x + z2*w2.x + bc.x;
                r.y = xv.y + z0*w0.y + z1*w1.y + z2*w2.y + bc.y;
                r.z = xv.z + z0*w0.z + z1*w1.z + z2*w2.z + bc.z;
                r.w = xv.w + z0*w0.w + z1*w1.w + z2*w2.w + bc.w;
                r0out[f] = r;
                vals[i*4+0]=r.x; vals[i*4+1]=r.y; vals[i*4+2]=r.z; vals[i*4+3]=r.w;
                sum += r.x + r.y + r.z + r.w;
                sq  += r.x*r.x + r.y*r.y + r.z*r.z + r.w*r.w;
            }
            #pragma unroll
            for (int o=16; o>0; o>>=1) {
                sum += __shfl_xor_sync(0xffffffffu, sum, o);
                sq  += __shfl_xor_sync(0xffffffffu, sq , o);
            }
            float mu   = sum * (1.f/CC);
            float var  = sq  * (1.f/CC) - mu*mu;
            float rstd = rsqrtf(var + LN_EPS);
            int par = (lrow >> 2) & 1;
            #pragma unroll
            for (int i=0; i<4; ++i) {
                int f = lane + 32*i;
                float4 g4 = ((const float4*)gamma)[f];
                float4 b4 = ((const float4*)beta )[f];
                float y0 = (vals[i*4+0]-mu)*rstd*g4.x + b4.x;
                float y1 = (vals[i*4+1]-mu)*rstd*g4.y + b4.y;
                float y2 = (vals[i*4+2]-mu)*rstd*g4.z + b4.z;
                float y3 = (vals[i*4+3]-mu)*rstd*g4.w + b4.w;
                int kc = (lane>>2) + 8*i;
                int ki = (lane&3)*4;
                int sw = (((ki>>3) ^ par) << 3) + (ki & 7);
                int off = kc*ACH + lrow*16 + sw;
                *(__half2*)(Ash+off)   = __halves2half2(__float2half_rn(y0), __float2half_rn(y1));
                *(__half2*)(Ash+off+2) = __halves2half2(__float2half_rn(y2), __float2half_rn(y3));
            }
        }
        __syncthreads();   // A ready; B scratch region free
    }

    // ---------------- main loop: 3-stage pipeline, BK=32 --------------------
    float acc[2][8][4];
    #pragma unroll
    for (int mt=0; mt<2; ++mt)
        #pragma unroll
        for (int nt=0; nt<8; ++nt)
            #pragma unroll
            for (int c=0; c<4; ++c) acc[mt][nt][c] = 0.f;

    // load one k16-chunk of B (8192 halves) into smem at dst (swizzled)
    #define LOADCH(kc_, dsth_) {                                            \
        __half* Bh_ = (dsth_);                                              \
        _Pragma("unroll")                                                   \
        for (int p_=0; p_<2; ++p_) {                                        \
            int c_ = t + p_*512;                                            \
            int n_ = c_ >> 1, gs_ = c_ & 1;                                 \
            int d_ = n_*16 + ((gs_ ^ ((n_>>2)&1)) << 3);                    \
            cp16(Bh_+d_, g_w2h + (size_t)(kc_)*8192 + c_*8);                \
        } }

    // prologue: stages 0 and 1 in flight
    LOADCH(0, Bbase);            LOADCH(1, Bbase + BCH);            cpcommit();
    LOADCH(2, Bbase + BSTG);     LOADCH(3, Bbase + BSTG + BCH);     cpcommit();

    #pragma unroll 1
    for (int it=0; it<16; ++it) {
        if (it < 15) cpwait<1>(); else cpwait<0>();
        __syncthreads();   // stage `it` data visible; stage it-1 fully consumed

        if (it < 14) {     // refill buffer (it+2)%3 (was stage it-1's buffer)
            __half* dst = Bbase + ((it+2)%3)*BSTG;
            LOADCH(2*(it+2),   dst);
            LOADCH(2*(it+2)+1, dst + BCH);
            cpcommit();
        }

        const __half* Bst = Bbase + (it%3)*BSTG;
        #pragma unroll
        for (int s=0; s<2; ++s) {
            int c = 2*it + s;
            const __half* Ah = Ash + c*ACH;
            const __half* Bh = Bst + s*BCH;

            unsigned ah[2][4];
            #pragma unroll
            for (int mt=0; mt<2; ++mt) {
                int r0r = mwarp*32 + mt*16 + grp;
                int r1r = r0r + 8;
                int p0 = ((r0r>>2)&1) << 3;
                int p1 = ((r1r>>2)&1) << 3;
                ah[mt][0] = *(const unsigned*)&Ah[r0r*16 + p0     + 2*cp];
                ah[mt][1] = *(const unsigned*)&Ah[r1r*16 + p1     + 2*cp];
                ah[mt][2] = *(const unsigned*)&Ah[r0r*16 + (8^p0) + 2*cp];
                ah[mt][3] = *(const unsigned*)&Ah[r1r*16 + (8^p1) + 2*cp];
            }
            #pragma unroll
            for (int nt=0; nt<8; ++nt) {
                int n  = nwarp*64 + nt*8 + grp;
                int pb = ((n>>2)&1) << 3;
                unsigned bh[2];
                bh[0] = *(const unsigned*)&Bh[n*16 + pb     + 2*cp];
                bh[1] = *(const unsigned*)&Bh[n*16 + (8^pb) + 2*cp];
                #pragma unroll
                for (int mt=0; mt<2; ++mt)
                    mma_fp16(acc[mt][nt], ah[mt], bh);
            }
        }
    }

    // ---------------- epilogue: +b2, +r0, LN, write out ---------------------
    float s[2][2], q[2][2];
    #pragma unroll
    for (int mt=0; mt<2; ++mt) {
        #pragma unroll
        for (int h=0; h<2; ++h) {
            int mrow = row0 + mwarp*32 + mt*16 + grp + 8*h;
            float ps = 0.f, pq = 0.f;
            #pragma unroll
            for (int nt=0; nt<8; ++nt) {
                int col = nwarp*64 + nt*8 + 2*cp;
                float2 r0v = *(const float2*)&g_r0[(size_t)mrow*CC + col];
                float2 bb  = *(const float2*)&b2[col];
                float v0 = acc[mt][nt][2*h+0] + bb.x + r0v.x;
                float v1 = acc[mt][nt][2*h+1] + bb.y + r0v.y;
                acc[mt][nt][2*h+0] = v0;
                acc[mt][nt][2*h+1] = v1;
                ps += v0 + v1;
                pq += v0*v0 + v1*v1;
            }
            s[mt][h] = ps; q[mt][h] = pq;
        }
    }
    #pragma unroll
    for (int mt=0; mt<2; ++mt)
        #pragma unroll
        for (int h=0; h<2; ++h) {
            s[mt][h] += __shfl_xor_sync(0xffffffffu, s[mt][h], 1);
            s[mt][h] += __shfl_xor_sync(0xffffffffu, s[mt][h], 2);
            q[mt][h] += __shfl_xor_sync(0xffffffffu, q[mt][h], 1);
            q[mt][h] += __shfl_xor_sync(0xffffffffu, q[mt][h], 2);
        }
    if (cp == 0) {
        #pragma unroll
        for (int mt=0; mt<2; ++mt)
            #pragma unroll
            for (int h=0; h<2; ++h) {
                int lr = mwarp*32 + mt*16 + grp + 8*h;
                csum[nwarp][lr] = s[mt][h];
                csq [nwarp][lr] = q[mt][h];
            }
    }
    __syncthreads();

    #pragma unroll
    for (int mt=0; mt<2; ++mt) {
        #pragma unroll
        for (int h=0; h<2; ++h) {
            int lr   = mwarp*32 + mt*16 + grp + 8*h;
            int mrow = row0 + lr;
            float ts = 0.f, tq = 0.f;
            #pragma unroll
            for (int ww=0; ww<8; ++ww) { ts += csum[ww][lr]; tq += csq[ww][lr]; }
            float mu   = ts * (1.f/CC);
            float var  = tq * (1.f/CC) - mu*mu;
            float rstd = rsqrtf(var + LN_EPS);
            #pragma unroll
            for (int nt=0; nt<8; ++nt) {
                int col = nwarp*64 + nt*8 + 2*cp;
                float2 gg = *(const float2*)&gamma[col];
                float2 ee = *(const float2*)&beta[col];
                float2 o;
                o.x = (acc[mt][nt][2*h+0] - mu) * rstd * gg.x + ee.x;
                o.y = (acc[mt][nt][2*h+1] - mu) * rstd * gg.y + ee.y;
                *(float2*)&out[(size_t)mrow*CC + col] = o;
            }
        }
    }
}

// ---------------------------------------------------------------------------
extern "C" void kernel_launch(void* const* d_in, const int* in_sizes, int n_in,
                              void* d_out, int out_size)
{
    const float* x     = (const float*)d_in[0];
    const float* wq    = (const float*)d_in[1];
    const float* bq    = (const float*)d_in[2];
    const float* wk    = (const float*)d_in[3];
    const float* bk    = (const float*)d_in[4];
    const float* wv    = (const float*)d_in[5];
    const float* bv    = (const float*)d_in[6];
    const float* wo    = (const float*)d_in[7];
    const float* bo    = (const float*)d_in[8];
    const float* w1    = (const float*)d_in[9];
    const float* b1    = (const float*)d_in[10];
    const float* w2    = (const float*)d_in[11];
    const float* b2    = (const float*)d_in[12];
    const float* gamma = (const float*)d_in[13];
    const float* beta  = (const float*)d_in[14];
    float* out = (float*)d_out;

    cudaFuncSetAttribute(gemm_fused, cudaFuncAttributeMaxDynamicSharedMemorySize, GEMM_SMEM);

    prep_all   <<<272, 256>>>(w2, wo, bo, w1, b1);
    qkv_kernel <<<RR/8, 256>>>(x, wq, bq, wk, bk, wv, bv);
    attn_kernel<<<BB*(SS/32), 256>>>();
    gemm_fused <<<RR/64, 512, GEMM_SMEM>>>(x, gamma, beta, b2, out);
}

// round 12
// speedup vs baseline: 1.0319x; 1.0319x over previous
#include <cuda_runtime.h>
#include <cuda_fp16.h>

// ---------------------------------------------------------------------------
//   q,k,v = x@W{q,k,v}^T + b   (d=3, heads share weights)
//   z3    = softmax(q k^T / sqrt(3)) v                    [B,S,3]
//   r0    = x + z3 @ Wc + bc          (Wc = wo_eff @ w1^T, [3,512])
//   y     = LN(r0)   -- fused into GEMM prologue, fp16 in smem
//   r     = r0 + y @ w2^T + b2        (single fp16 mma.sync term)
//   out   = LN(r)
// ---------------------------------------------------------------------------

#define BB   8
#define SS   2048
#define CC   512
#define RR   (BB*SS)          // 16384 rows
#define LN_EPS 1e-5f

// Scratch (device globals: allocation-free)
__device__ __align__(16) float  g_q [RR*3];
__device__ __align__(16) float  g_k [BB*3*SS];    // [b][d][s]
__device__ __align__(16) float  g_v [BB*3*SS];
__device__ __align__(16) float  g_z [RR*3];
__device__ __align__(16) float  g_Wc[3*CC];       // [d][c]
__device__ __align__(16) float  g_bc[CC];
__device__ __align__(16) float  g_r0[RR*CC];
// w2 in fp16, chunked layout [k/16][n][16]
__device__ __align__(16) __half g_w2h[CC*CC];

__device__ __forceinline__ float ex2f(float x)
{
    float r;
    asm("ex2.approx.ftz.f32 %0, %1;" : "=f"(r) : "f"(x));
    return r;
}

// ---------------------------------------------------------------------------
// Kernel 1 (fused prep): blocks 0..255 convert w2 -> fp16 chunked image;
// blocks 256..271 compute Wc = wo_eff @ w1^T and bc (parallelized:
// each block 32 outputs, 8 lanes split the 512-long dot).
// 256 threads per block.
// ---------------------------------------------------------------------------
__global__ void prep_all(const float* __restrict__ w2,
                         const float* __restrict__ wo, const float* __restrict__ bo,
                         const float* __restrict__ w1, const float* __restrict__ b1)
{
    if (blockIdx.x < 256) {
        int idx = blockIdx.x*256 + threadIdx.x;     // 0..65535
        float4 v = ((const float4*)w2)[idx];
        int n  = (idx*4) >> 9;
        int k  = (idx*4) & 511;
        int kc = k >> 4, ki = k & 15;
        size_t dst = (size_t)kc*(CC*16) + (size_t)n*16 + ki;
        ((__half2*)(g_w2h + dst))[0] = __halves2half2(__float2half_rn(v.x), __float2half_rn(v.y));
        ((__half2*)(g_w2h + dst))[1] = __halves2half2(__float2half_rn(v.z), __float2half_rn(v.w));
        return;
    }
    // ---- Wc/bc prep ----
    __shared__ __align__(16) float woe[CC*3];
    __shared__ __align__(16) float sbo[CC];
    int t = threadIdx.x;
    for (int j=t; j<CC; j+=256) {
        const float* row = wo + j*18;
        float s0=0.f, s1=0.f, s2=0.f;
        #pragma unroll
        for (int h=0; h<6; ++h) { s0 += row[h*3+0]; s1 += row[h*3+1]; s2 += row[h*3+2]; }
        woe[j*3+0]=s0; woe[j*3+1]=s1; woe[j*3+2]=s2; sbo[j]=bo[j];
    }
    __syncthreads();

    int to = (blockIdx.x - 256)*32 + (t >> 3);   // output channel
    int ln = t & 7;                              // 8 lanes per output
    const float* w1row = w1 + (size_t)to*CC + ln*64;
    float a0=0.f, a1=0.f, a2=0.f, ab=0.f;
    #pragma unroll 8
    for (int j=0; j<64; ++j) {
        float w = w1row[j];
        int jj = ln*64 + j;
        a0 += woe[jj*3+0]*w; a1 += woe[jj*3+1]*w; a2 += woe[jj*3+2]*w; ab += sbo[jj]*w;
    }
    #pragma unroll
    for (int o=4; o>0; o>>=1) {
        a0 += __shfl_xor_sync(0xffffffffu, a0, o);
        a1 += __shfl_xor_sync(0xffffffffu, a1, o);
        a2 += __shfl_xor_sync(0xffffffffu, a2, o);
        ab += __shfl_xor_sync(0xffffffffu, ab, o);
    }
    if (ln == 0) {
        g_Wc[0*CC+to]=a0; g_Wc[1*CC+to]=a1; g_Wc[2*CC+to]=a2;
        g_bc[to] = ab + b1[to];
    }
}

// ---------------------------------------------------------------------------
// Kernel 2: q,k,v projections. One warp per row, 8 rows/block, grid = RR/8.
// q pre-scaled by log2(e)/sqrt(3) so attention can use raw ex2.
// ---------------------------------------------------------------------------
__global__ void qkv_kernel(const float* __restrict__ x,
                           const float* __restrict__ wq, const float* __restrict__ bq,
                           const float* __restrict__ wk, const float* __restrict__ bk,
                           const float* __restrict__ wv, const float* __restrict__ bv)
{
    __shared__ __align__(16) float sw[9*CC];
    int t = threadIdx.x;
    for (int i=t; i<3*CC; i+=256) {
        sw[i]        = wq[i];
        sw[3*CC + i] = wk[i];
        sw[6*CC + i] = wv[i];
    }
    __syncthreads();

    int warp = t >> 5, lane = t & 31;
    int m = blockIdx.x*8 + warp;

    const float4* x4  = (const float4*)(x + (size_t)m*CC);
    const float4* sw4 = (const float4*)sw;

    float acc[9];
    #pragma unroll
    for (int r=0; r<9; ++r) acc[r] = 0.f;

    #pragma unroll
    for (int i=0; i<4; ++i) {
        int f = lane + 32*i;
        float4 xv = x4[f];
        #pragma unroll
        for (int r=0; r<9; ++r) {
            float4 w = sw4[r*128 + f];
            acc[r] += xv.x*w.x + xv.y*w.y + xv.z*w.z + xv.w*w.w;
        }
    }
    #pragma unroll
    for (int r=0; r<9; ++r) {
        #pragma unroll
        for (int o=16; o>0; o>>=1) acc[r] += __shfl_xor_sync(0xffffffffu, acc[r], o);
    }
    if (lane == 0) {
        int b = m >> 11, s = m & (SS-1);
        const float inv = 0.83296790143f;   // log2(e)/sqrt(3)
        #pragma unroll
        for (int d=0; d<3; ++d) {
            g_q[m*3+d]            = (acc[d]   + bq[d]) * inv;
            g_k[(b*3+d)*SS + s]   =  acc[3+d] + bk[d];
            g_v[(b*3+d)*SS + s]   =  acc[6+d] + bv[d];
        }
    }
}

// ---------------------------------------------------------------------------
// Kernel 3: attention, d=3, 32 queries/block (512 blocks). exp == ex2.
// ---------------------------------------------------------------------------
__global__ void __launch_bounds__(256, 2) attn_kernel()
{
    __shared__ __align__(16) float sKV[6][SS];    // 48 KB
    int t = threadIdx.x;
    int b  = blockIdx.x >> 6;
    int q0 = (blockIdx.x & 63) * 32;

    {   // bulk load K and V
        const float4* gk4 = (const float4*)(g_k + b*3*SS);
        const float4* gv4 = (const float4*)(g_v + b*3*SS);
        float4* s4 = (float4*)sKV;
        for (int i=t; i<3*SS/4; i+=256) { s4[i] = gk4[i]; s4[1536 + i] = gv4[i]; }
    }
    __syncthreads();

    int warp = t >> 5, lane = t & 31;
    const float4* K0 = (const float4*)sKV[0];
    const float4* K1 = (const float4*)sKV[1];
    const float4* K2 = (const float4*)sKV[2];
    const float4* V0 = (const float4*)sKV[3];
    const float4* V1 = (const float4*)sKV[4];
    const float4* V2 = (const float4*)sKV[5];

    #pragma unroll 1
    for (int p=0; p<2; ++p) {
        int m = b*SS + q0 + warp*4 + p*2;
        float qa0=g_q[m*3+0], qb0=g_q[m*3+1], qc0=g_q[m*3+2];
        float qa1=g_q[m*3+3], qb1=g_q[m*3+4], qc1=g_q[m*3+5];
        float ss0=0.f, a00=0.f, a01=0.f, a02=0.f;
        float ss1=0.f, a10=0.f, a11=0.f, a12=0.f;
        #pragma unroll 4
        for (int i=0; i<16; ++i) {
            int j = lane + 32*i;
            float4 k0 = K0[j], k1 = K1[j], k2 = K2[j];
            float4 v0 = V0[j], v1 = V1[j], v2 = V2[j];
            float e;
            e = ex2f(qa0*k0.x + qb0*k1.x + qc0*k2.x); ss0+=e; a00+=e*v0.x; a01+=e*v1.x; a02+=e*v2.x;
            e = ex2f(qa1*k0.x + qb1*k1.x + qc1*k2.x); ss1+=e; a10+=e*v0.x; a11+=e*v1.x; a12+=e*v2.x;
            e = ex2f(qa0*k0.y + qb0*k1.y + qc0*k2.y); ss0+=e; a00+=e*v0.y; a01+=e*v1.y; a02+=e*v2.y;
            e = ex2f(qa1*k0.y + qb1*k1.y + qc1*k2.y); ss1+=e; a10+=e*v0.y; a11+=e*v1.y; a12+=e*v2.y;
            e = ex2f(qa0*k0.z + qb0*k1.z + qc0*k2.z); ss0+=e; a00+=e*v0.z; a01+=e*v1.z; a02+=e*v2.z;
            e = ex2f(qa1*k0.z + qb1*k1.z + qc1*k2.z); ss1+=e; a10+=e*v0.z; a11+=e*v1.z; a12+=e*v2.z;
            e = ex2f(qa0*k0.w + qb0*k1.w + qc0*k2.w); ss0+=e; a00+=e*v0.w; a01+=e*v1.w; a02+=e*v2.w;
            e = ex2f(qa1*k0.w + qb1*k1.w + qc1*k2.w); ss1+=e; a10+=e*v0.w; a11+=e*v1.w; a12+=e*v2.w;
        }
        #pragma unroll
        for (int o=16; o>0; o>>=1) {
            ss0 += __shfl_xor_sync(0xffffffffu, ss0, o);
            a00 += __shfl_xor_sync(0xffffffffu, a00, o);
            a01 += __shfl_xor_sync(0xffffffffu, a01, o);
            a02 += __shfl_xor_sync(0xffffffffu, a02, o);
            ss1 += __shfl_xor_sync(0xffffffffu, ss1, o);
            a10 += __shfl_xor_sync(0xffffffffu, a10, o);
            a11 += __shfl_xor_sync(0xffffffffu, a11, o);
            a12 += __shfl_xor_sync(0xffffffffu, a12, o);
        }
        if (lane == 0) {
            float i0 = 1.f/ss0, i1 = 1.f/ss1;
            g_z[m*3+0] = a00*i0; g_z[m*3+1] = a01*i0; g_z[m*3+2] = a02*i0;
            g_z[m*3+3] = a10*i1; g_z[m*3+4] = a11*i1; g_z[m*3+5] = a12*i1;
        }
    }
}

// ---------------------------------------------------------------------------
// Kernel 4 (fused): r0 = x + z@Wc + bc ; y = LN(r0) -> smem fp16 ;
// r1 = y @ w2^T ; r = r0 + r1 + b2 ; out = LN(r).
// BM=64, BN=512 (full row), BK=32 (16 iterations), 512 threads.
// 3-stage cp.async pipeline for B; ONE barrier per iteration (top-of-iter
// sync doubles as data-ready + prev-buffer-consumed guard).
// ---------------------------------------------------------------------------
#define ACH  1032                 // halves per A k16-chunk (64*16 + 8 pad)
#define ASZ  (32*ACH)             // 33024 halves total for A
#define BCH  8192                 // halves per B k16-chunk in smem
#define BSTG (2*BCH)              // halves per pipeline stage (BK=32)
#define GEMM_SMEM ((ASZ + 3*BSTG)*2)   // 164352 bytes

__device__ __forceinline__ void mma_fp16(float d[4], const unsigned a[4], const unsigned b[2])
{
    asm volatile(
        "mma.sync.aligned.m16n8k16.row.col.f32.f16.f16.f32 "
        "{%0,%1,%2,%3}, {%4,%5,%6,%7}, {%8,%9}, {%0,%1,%2,%3};\n"
        : "+f"(d[0]), "+f"(d[1]), "+f"(d[2]), "+f"(d[3])
        : "r"(a[0]), "r"(a[1]), "r"(a[2]), "r"(a[3]), "r"(b[0]), "r"(b[1]));
}
__device__ __forceinline__ void cp16(void* smem, const void* gmem)
{
    unsigned sa = (unsigned)__cvta_generic_to_shared(smem);
    asm volatile("cp.async.cg.shared.global [%0], [%1], 16;\n" :: "r"(sa), "l"(gmem));
}
__device__ __forceinline__ void cpcommit() { asm volatile("cp.async.commit_group;\n" ::: "memory"); }
template<int N> __device__ __forceinline__ void cpwait() { asm volatile("cp.async.wait_group %0;\n" :: "n"(N) : "memory"); }

__global__ void __launch_bounds__(512, 1)
gemm_fused(const float* __restrict__ x,
           const float* __restrict__ gamma, const float* __restrict__ beta,
           const float* __restrict__ b2, float* __restrict__ out)
{
    extern __shared__ __half sdyn[];
    __half* Ash   = sdyn;
    __half* Bbase = sdyn + ASZ;
    __shared__ float csum[8][64], csq[8][64];

    int t = threadIdx.x;
    int w = t >> 5, lane = t & 31;
    int grp = lane >> 2, cp = lane & 3;
    int mwarp = w >> 3, nwarp = w & 7;
    int row0 = blockIdx.x * 64;

    // ---------------- prologue: r0 + LN + fp16 into Ash ---------------------
    {
        float* sWc = (float*)Bbase;            // scratch inside B region
        float* sbc = sWc + 3*CC;
        for (int i=t; i<3*CC; i+=512) sWc[i] = g_Wc[i];
        for (int i=t; i<CC;   i+=512) sbc[i] = g_bc[i];
        __syncthreads();

        #pragma unroll 1
        for (int rr=0; rr<4; ++rr) {
            int lrow = w*4 + rr;
            int m = row0 + lrow;
            float z0 = g_z[m*3+0], z1 = g_z[m*3+1], z2 = g_z[m*3+2];
            const float4* x4 = (const float4*)(x + (size_t)m*CC);
            float4* r0out = (float4*)(g_r0 + (size_t)m*CC);
            float vals[16];
            float sum = 0.f, sq = 0.f;
            #pragma unroll
            for (int i=0; i<4; ++i) {
                int f = lane + 32*i;
                float4 xv = x4[f];
                float4 w0 = ((const float4*)sWc)[f];
                float4 w1 = ((const float4*)sWc)[128+f];
                float4 w2 = ((const float4*)sWc)[256+f];
                float4 bc = ((const float4*)sbc)[f];
                float4 r;
                r.x = xv.x + z0*w0.x + z1*w1.x + z2*w2.x + bc.x;
                r.y = xv.y + z0*w0.y + z1*w1.y + z2*w2.y + bc.y;
                r.z = xv.z + z0*w0.z + z1*w1.z + z2*w2.z + bc.z;
                r.w = xv.w + z0*w0.w + z1*w1.w + z2*w2.w + bc.w;
                r0out[f] = r;
                vals[i*4+0]=r.x; vals[i*4+1]=r.y; vals[i*4+2]=r.z; vals[i*4+3]=r.w;
                sum += r.x + r.y + r.z + r.w;
                sq  += r.x*r.x + r.y*r.y + r.z*r.z + r.w*r.w;
            }
            #pragma unroll
            for (int o=16; o>0; o>>=1) {
                sum += __shfl_xor_sync(0xffffffffu, sum, o);
                sq  += __shfl_xor_sync(0xffffffffu, sq , o);
            }
            float mu   = sum * (1.f/CC);
            float var  = sq  * (1.f/CC) - mu*mu;
            float rstd = rsqrtf(var + LN_EPS);
            int par = (lrow >> 2) & 1;
            #pragma unroll
            for (int i=0; i<4; ++i) {
                int f = lane + 32*i;
                float4 g4 = ((const float4*)gamma)[f];
                float4 b4 = ((const float4*)beta )[f];
                float y0 = (vals[i*4+0]-mu)*rstd*g4.x + b4.x;
                float y1 = (vals[i*4+1]-mu)*rstd*g4.y + b4.y;
                float y2 = (vals[i*4+2]-mu)*rstd*g4.z + b4.z;
                float y3 = (vals[i*4+3]-mu)*rstd*g4.w + b4.w;
                int kc = (lane>>2) + 8*i;
                int ki = (lane&3)*4;
                int sw = (((ki>>3) ^ par) << 3) + (ki & 7);
                int off = kc*ACH + lrow*16 + sw;
                *(__half2*)(Ash+off)   = __halves2half2(__float2half_rn(y0), __float2half_rn(y1));
                *(__half2*)(Ash+off+2) = __halves2half2(__float2half_rn(y2), __float2half_rn(y3));
            }
        }
        __syncthreads();   // A ready; B scratch region free
    }

    // ---------------- main loop: 3-stage pipeline, BK=32 --------------------
    float acc[2][8][4];
    #pragma unroll
    for (int mt=0; mt<2; ++mt)
        #pragma unroll
        for (int nt=0; nt<8; ++nt)
            #pragma unroll
            for (int c=0; c<4; ++c) acc[mt][nt][c] = 0.f;

    // load one k16-chunk of B (8192 halves) into smem at dst (swizzled)
    #define LOADCH(kc_, dsth_) {                                            \
        __half* Bh_ = (dsth_);                                              \
        _Pragma("unroll")                                                   \
        for (int p_=0; p_<2; ++p_) {                                        \
            int c_ = t + p_*512;                                            \
            int n_ = c_ >> 1, gs_ = c_ & 1;                                 \
            int d_ = n_*16 + ((gs_ ^ ((n_>>2)&1)) << 3);                    \
            cp16(Bh_+d_, g_w2h + (size_t)(kc_)*8192 + c_*8);                \
        } }

    // prologue: stages 0 and 1 in flight
    LOADCH(0, Bbase);            LOADCH(1, Bbase + BCH);            cpcommit();
    LOADCH(2, Bbase + BSTG);     LOADCH(3, Bbase + BSTG + BCH);     cpcommit();

    #pragma unroll 1
    for (int it=0; it<16; ++it) {
        if (it < 15) cpwait<1>(); else cpwait<0>();
        __syncthreads();   // stage `it` data visible; stage it-1 fully consumed

        if (it < 14) {     // refill buffer (it+2)%3 (was stage it-1's buffer)
            __half* dst = Bbase + ((it+2)%3)*BSTG;
            LOADCH(2*(it+2),   dst);
            LOADCH(2*(it+2)+1, dst + BCH);
            cpcommit();
        }

        const __half* Bst = Bbase + (it%3)*BSTG;
        #pragma unroll
        for (int s=0; s<2; ++s) {
            int c = 2*it + s;
            const __half* Ah = Ash + c*ACH;
            const __half* Bh = Bst + s*BCH;

            unsigned ah[2][4];
            #pragma unroll
            for (int mt=0; mt<2; ++mt) {
                int r0r = mwarp*32 + mt*16 + grp;
                int r1r = r0r + 8;
                int p0 = ((r0r>>2)&1) << 3;
                int p1 = ((r1r>>2)&1) << 3;
                ah[mt][0] = *(const unsigned*)&Ah[r0r*16 + p0     + 2*cp];
                ah[mt][1] = *(const unsigned*)&Ah[r1r*16 + p1     + 2*cp];
                ah[mt][2] = *(const unsigned*)&Ah[r0r*16 + (8^p0) + 2*cp];
                ah[mt][3] = *(const unsigned*)&Ah[r1r*16 + (8^p1) + 2*cp];
            }
            #pragma unroll
            for (int nt=0; nt<8; ++nt) {
                int n  = nwarp*64 + nt*8 + grp;
                int pb = ((n>>2)&1) << 3;
                unsigned bh[2];
                bh[0] = *(const unsigned*)&Bh[n*16 + pb     + 2*cp];
                bh[1] = *(const unsigned*)&Bh[n*16 + (8^pb) + 2*cp];
                #pragma unroll
                for (int mt=0; mt<2; ++mt)
                    mma_fp16(acc[mt][nt], ah[mt], bh);
            }
        }
    }

    // ---------------- epilogue: +b2, +r0, LN, write out ---------------------
    float s[2][2], q[2][2];
    #pragma unroll
    for (int mt=0; mt<2; ++mt) {
        #pragma unroll
        for (int h=0; h<2; ++h) {
            int mrow = row0 + mwarp*32 + mt*16 + grp + 8*h;
            float ps = 0.f, pq = 0.f;
            #pragma unroll
            for (int nt=0; nt<8; ++nt) {
                int col = nwarp*64 + nt*8 + 2*cp;
                float2 r0v = *(const float2*)&g_r0[(size_t)mrow*CC + col];
                float2 bb  = *(const float2*)&b2[col];
                float v0 = acc[mt][nt][2*h+0] + bb.x + r0v.x;
                float v1 = acc[mt][nt][2*h+1] + bb.y + r0v.y;
                acc[mt][nt][2*h+0] = v0;
                acc[mt][nt][2*h+1] = v1;
                ps += v0 + v1;
                pq += v0*v0 + v1*v1;
            }
            s[mt][h] = ps; q[mt][h] = pq;
        }
    }
    #pragma unroll
    for (int mt=0; mt<2; ++mt)
        #pragma unroll
        for (int h=0; h<2; ++h) {
            s[mt][h] += __shfl_xor_sync(0xffffffffu, s[mt][h], 1);
            s[mt][h] += __shfl_xor_sync(0xffffffffu, s[mt][h], 2);
            q[mt][h] += __shfl_xor_sync(0xffffffffu, q[mt][h], 1);
            q[mt][h] += __shfl_xor_sync(0xffffffffu, q[mt][h], 2);
        }
    if (cp == 0) {
        #pragma unroll
        for (int mt=0; mt<2; ++mt)
            #pragma unroll
            for (int h=0; h<2; ++h) {
                int lr = mwarp*32 + mt*16 + grp + 8*h;
                csum[nwarp][lr] = s[mt][h];
                csq [nwarp][lr] = q[mt][h];
            }
    }
    __syncthreads();

    #pragma unroll
    for (int mt=0; mt<2; ++mt) {
        #pragma unroll
        for (int h=0; h<2; ++h) {
            int lr   = mwarp*32 + mt*16 + grp + 8*h;
            int mrow = row0 + lr;
            float ts = 0.f, tq = 0.f;
            #pragma unroll
            for (int ww=0; ww<8; ++ww) { ts += csum[ww][lr]; tq += csq[ww][lr]; }
            float mu   = ts * (1.f/CC);
            float var  = tq * (1.f/CC) - mu*mu;
            float rstd = rsqrtf(var + LN_EPS);
            #pragma unroll
            for (int nt=0; nt<8; ++nt) {
                int col = nwarp*64 + nt*8 + 2*cp;
                float2 gg = *(const float2*)&gamma[col];
                float2 ee = *(const float2*)&beta[col];
                float2 o;
                o.x = (acc[mt][nt][2*h+0] - mu) * rstd * gg.x + ee.x;
                o.y = (acc[mt][nt][2*h+1] - mu) * rstd * gg.y + ee.y;
                *(float2*)&out[(size_t)mrow*CC + col] = o;
            }
        }
    }
}

// ---------------------------------------------------------------------------
extern "C" void kernel_launch(void* const* d_in, const int* in_sizes, int n_in,
                              void* d_out, int out_size)
{
    const float* x     = (const float*)d_in[0];
    const float* wq    = (const float*)d_in[1];
    const float* bq    = (const float*)d_in[2];
    const float* wk    = (const float*)d_in[3];
    const float* bk    = (const float*)d_in[4];
    const float* wv    = (const float*)d_in[5];
    const float* bv    = (const float*)d_in[6];
    const float* wo    = (const float*)d_in[7];
    const float* bo    = (const float*)d_in[8];
    const float* w1    = (const float*)d_in[9];
    const float* b1    = (const float*)d_in[10];
    const float* w2    = (const float*)d_in[11];
    const float* b2    = (const float*)d_in[12];
    const float* gamma = (const float*)d_in[13];
    const float* beta  = (const float*)d_in[14];
    float* out = (float*)d_out;

    cudaFuncSetAttribute(gemm_fused, cudaFuncAttributeMaxDynamicSharedMemorySize, GEMM_SMEM);

    prep_all   <<<272, 256>>>(w2, wo, bo, w1, b1);
    qkv_kernel <<<RR/8, 256>>>(x, wq, bq, wk, bk, wv, bv);
    attn_kernel<<<BB*(SS/32), 256>>>();
    gemm_fused <<<RR/64, 512, GEMM_SMEM>>>(x, gamma, beta, b2, out);
}

// round 13
// speedup vs baseline: 1.0351x; 1.0030x over previous
#include <cuda_runtime.h>
#include <cuda_fp16.h>

// ---------------------------------------------------------------------------
//   q,k,v = x@W{q,k,v}^T + b   (d=3, heads share weights)
//   z3    = softmax(q k^T / sqrt(3)) v                    [B,S,3]
//   r0    = x + z3 @ Wc + bc          (Wc = wo_eff @ w1^T, [3,512])
//   y     = LN(r0)   -- fused into GEMM prologue, fp16 in smem
//   r     = r0 + y @ w2^T + b2        (single fp16 mma.sync term)
//   out   = LN(r)
// ---------------------------------------------------------------------------

#define BB   8
#define SS   2048
#define CC   512
#define RR   (BB*SS)          // 16384 rows
#define LN_EPS 1e-5f

// Scratch (device globals: allocation-free)
__device__ __align__(16) float  g_q [RR*3];
__device__ __align__(16) float  g_k [BB*3*SS];    // [b][d][s]
__device__ __align__(16) float  g_v [BB*3*SS];
__device__ __align__(16) float  g_z [RR*3];
__device__ __align__(16) float  g_Wc[3*CC];       // [d][c]
__device__ __align__(16) float  g_bc[CC];
__device__ __align__(16) float  g_r0[RR*CC];
// w2 in fp16, chunked layout [k/16][n][16]
__device__ __align__(16) __half g_w2h[CC*CC];

__device__ __forceinline__ float ex2f(float x)
{
    float r;
    asm("ex2.approx.ftz.f32 %0, %1;" : "=f"(r) : "f"(x));
    return r;
}

// ---------------------------------------------------------------------------
// Kernel 1 (fused prep): blocks 0..255 convert w2 -> fp16 chunked image;
// blocks 256..271 compute Wc = wo_eff @ w1^T and bc (parallelized:
// each block 32 outputs, 8 lanes split the 512-long dot).
// 256 threads per block.
// ---------------------------------------------------------------------------
__global__ void prep_all(const float* __restrict__ w2,
                         const float* __restrict__ wo, const float* __restrict__ bo,
                         const float* __restrict__ w1, const float* __restrict__ b1)
{
    if (blockIdx.x < 256) {
        int idx = blockIdx.x*256 + threadIdx.x;     // 0..65535
        float4 v = ((const float4*)w2)[idx];
        int n  = (idx*4) >> 9;
        int k  = (idx*4) & 511;
        int kc = k >> 4, ki = k & 15;
        size_t dst = (size_t)kc*(CC*16) + (size_t)n*16 + ki;
        ((__half2*)(g_w2h + dst))[0] = __halves2half2(__float2half_rn(v.x), __float2half_rn(v.y));
        ((__half2*)(g_w2h + dst))[1] = __halves2half2(__float2half_rn(v.z), __float2half_rn(v.w));
        return;
    }
    // ---- Wc/bc prep ----
    __shared__ __align__(16) float woe[CC*3];
    __shared__ __align__(16) float sbo[CC];
    int t = threadIdx.x;
    for (int j=t; j<CC; j+=256) {
        const float* row = wo + j*18;
        float s0=0.f, s1=0.f, s2=0.f;
        #pragma unroll
        for (int h=0; h<6; ++h) { s0 += row[h*3+0]; s1 += row[h*3+1]; s2 += row[h*3+2]; }
        woe[j*3+0]=s0; woe[j*3+1]=s1; woe[j*3+2]=s2; sbo[j]=bo[j];
    }
    __syncthreads();

    int to = (blockIdx.x - 256)*32 + (t >> 3);   // output channel
    int ln = t & 7;                              // 8 lanes per output
    const float* w1row = w1 + (size_t)to*CC + ln*64;
    float a0=0.f, a1=0.f, a2=0.f, ab=0.f;
    #pragma unroll 8
    for (int j=0; j<64; ++j) {
        float w = w1row[j];
        int jj = ln*64 + j;
        a0 += woe[jj*3+0]*w; a1 += woe[jj*3+1]*w; a2 += woe[jj*3+2]*w; ab += sbo[jj]*w;
    }
    #pragma unroll
    for (int o=4; o>0; o>>=1) {
        a0 += __shfl_xor_sync(0xffffffffu, a0, o);
        a1 += __shfl_xor_sync(0xffffffffu, a1, o);
        a2 += __shfl_xor_sync(0xffffffffu, a2, o);
        ab += __shfl_xor_sync(0xffffffffu, ab, o);
    }
    if (ln == 0) {
        g_Wc[0*CC+to]=a0; g_Wc[1*CC+to]=a1; g_Wc[2*CC+to]=a2;
        g_bc[to] = ab + b1[to];
    }
}

// ---------------------------------------------------------------------------
// Kernel 2: q,k,v projections. One warp per row, 8 rows/block, grid = RR/8.
// q pre-scaled by log2(e)/sqrt(3) so attention can use raw ex2.
// ---------------------------------------------------------------------------
__global__ void qkv_kernel(const float* __restrict__ x,
                           const float* __restrict__ wq, const float* __restrict__ bq,
                           const float* __restrict__ wk, const float* __restrict__ bk,
                           const float* __restrict__ wv, const float* __restrict__ bv)
{
    __shared__ __align__(16) float sw[9*CC];
    int t = threadIdx.x;
    for (int i=t; i<3*CC; i+=256) {
        sw[i]        = wq[i];
        sw[3*CC + i] = wk[i];
        sw[6*CC + i] = wv[i];
    }
    __syncthreads();

    int warp = t >> 5, lane = t & 31;
    int m = blockIdx.x*8 + warp;

    const float4* x4  = (const float4*)(x + (size_t)m*CC);
    const float4* sw4 = (const float4*)sw;

    float acc[9];
    #pragma unroll
    for (int r=0; r<9; ++r) acc[r] = 0.f;

    #pragma unroll
    for (int i=0; i<4; ++i) {
        int f = lane + 32*i;
        float4 xv = x4[f];
        #pragma unroll
        for (int r=0; r<9; ++r) {
            float4 w = sw4[r*128 + f];
            acc[r] += xv.x*w.x + xv.y*w.y + xv.z*w.z + xv.w*w.w;
        }
    }
    #pragma unroll
    for (int r=0; r<9; ++r) {
        #pragma unroll
        for (int o=16; o>0; o>>=1) acc[r] += __shfl_xor_sync(0xffffffffu, acc[r], o);
    }
    if (lane == 0) {
        int b = m >> 11, s = m & (SS-1);
        const float inv = 0.83296790143f;   // log2(e)/sqrt(3)
        #pragma unroll
        for (int d=0; d<3; ++d) {
            g_q[m*3+d]            = (acc[d]   + bq[d]) * inv;
            g_k[(b*3+d)*SS + s]   =  acc[3+d] + bk[d];
            g_v[(b*3+d)*SS + s]   =  acc[6+d] + bv[d];
        }
    }
}

// ---------------------------------------------------------------------------
// Kernel 3: attention, d=3, 32 queries/block (512 blocks). exp == ex2.
// ---------------------------------------------------------------------------
__global__ void __launch_bounds__(256, 2) attn_kernel()
{
    __shared__ __align__(16) float sKV[6][SS];    // 48 KB
    int t = threadIdx.x;
    int b  = blockIdx.x >> 6;
    int q0 = (blockIdx.x & 63) * 32;

    {   // bulk load K and V
        const float4* gk4 = (const float4*)(g_k + b*3*SS);
        const float4* gv4 = (const float4*)(g_v + b*3*SS);
        float4* s4 = (float4*)sKV;
        for (int i=t; i<3*SS/4; i+=256) { s4[i] = gk4[i]; s4[1536 + i] = gv4[i]; }
    }
    __syncthreads();

    int warp = t >> 5, lane = t & 31;
    const float4* K0 = (const float4*)sKV[0];
    const float4* K1 = (const float4*)sKV[1];
    const float4* K2 = (const float4*)sKV[2];
    const float4* V0 = (const float4*)sKV[3];
    const float4* V1 = (const float4*)sKV[4];
    const float4* V2 = (const float4*)sKV[5];

    #pragma unroll 1
    for (int p=0; p<2; ++p) {
        int m = b*SS + q0 + warp*4 + p*2;
        float qa0=g_q[m*3+0], qb0=g_q[m*3+1], qc0=g_q[m*3+2];
        float qa1=g_q[m*3+3], qb1=g_q[m*3+4], qc1=g_q[m*3+5];
        float ss0=0.f, a00=0.f, a01=0.f, a02=0.f;
        float ss1=0.f, a10=0.f, a11=0.f, a12=0.f;
        #pragma unroll 4
        for (int i=0; i<16; ++i) {
            int j = lane + 32*i;
            float4 k0 = K0[j], k1 = K1[j], k2 = K2[j];
            float4 v0 = V0[j], v1 = V1[j], v2 = V2[j];
            float e;
            e = ex2f(qa0*k0.x + qb0*k1.x + qc0*k2.x); ss0+=e; a00+=e*v0.x; a01+=e*v1.x; a02+=e*v2.x;
            e = ex2f(qa1*k0.x + qb1*k1.x + qc1*k2.x); ss1+=e; a10+=e*v0.x; a11+=e*v1.x; a12+=e*v2.x;
            e = ex2f(qa0*k0.y + qb0*k1.y + qc0*k2.y); ss0+=e; a00+=e*v0.y; a01+=e*v1.y; a02+=e*v2.y;
            e = ex2f(qa1*k0.y + qb1*k1.y + qc1*k2.y); ss1+=e; a10+=e*v0.y; a11+=e*v1.y; a12+=e*v2.y;
            e = ex2f(qa0*k0.z + qb0*k1.z + qc0*k2.z); ss0+=e; a00+=e*v0.z; a01+=e*v1.z; a02+=e*v2.z;
            e = ex2f(qa1*k0.z + qb1*k1.z + qc1*k2.z); ss1+=e; a10+=e*v0.z; a11+=e*v1.z; a12+=e*v2.z;
            e = ex2f(qa0*k0.w + qb0*k1.w + qc0*k2.w); ss0+=e; a00+=e*v0.w; a01+=e*v1.w; a02+=e*v2.w;
            e = ex2f(qa1*k0.w + qb1*k1.w + qc1*k2.w); ss1+=e; a10+=e*v0.w; a11+=e*v1.w; a12+=e*v2.w;
        }
        #pragma unroll
        for (int o=16; o>0; o>>=1) {
            ss0 += __shfl_xor_sync(0xffffffffu, ss0, o);
            a00 += __shfl_xor_sync(0xffffffffu, a00, o);
            a01 += __shfl_xor_sync(0xffffffffu, a01, o);
            a02 += __shfl_xor_sync(0xffffffffu, a02, o);
            ss1 += __shfl_xor_sync(0xffffffffu, ss1, o);
            a10 += __shfl_xor_sync(0xffffffffu, a10, o);
            a11 += __shfl_xor_sync(0xffffffffu, a11, o);
            a12 += __shfl_xor_sync(0xffffffffu, a12, o);
        }
        if (lane == 0) {
            float i0 = 1.f/ss0, i1 = 1.f/ss1;
            g_z[m*3+0] = a00*i0; g_z[m*3+1] = a01*i0; g_z[m*3+2] = a02*i0;
            g_z[m*3+3] = a10*i1; g_z[m*3+4] = a11*i1; g_z[m*3+5] = a12*i1;
        }
    }
}

// ---------------------------------------------------------------------------
// Kernel 4 (fused): r0 = x + z@Wc + bc ; y = LN(r0) -> smem fp16 ;
// r1 = y @ w2^T ; r = r0 + r1 + b2 ; out = LN(r).
// BM=64, BN=512 (full row), BK=32 (16 iterations), 512 threads.
// 3-stage cp.async pipeline for B; ONE barrier per iteration (top-of-iter
// sync doubles as data-ready + prev-buffer-consumed guard).
// ---------------------------------------------------------------------------
#define ACH  1032                 // halves per A k16-chunk (64*16 + 8 pad)
#define ASZ  (32*ACH)             // 33024 halves total for A
#define BCH  8192                 // halves per B k16-chunk in smem
#define BSTG (2*BCH)              // halves per pipeline stage (BK=32)
#define GEMM_SMEM ((ASZ + 3*BSTG)*2)   // 164352 bytes

__device__ __forceinline__ void mma_fp16(float d[4], const unsigned a[4], const unsigned b[2])
{
    asm volatile(
        "mma.sync.aligned.m16n8k16.row.col.f32.f16.f16.f32 "
        "{%0,%1,%2,%3}, {%4,%5,%6,%7}, {%8,%9}, {%0,%1,%2,%3};\n"
        : "+f"(d[0]), "+f"(d[1]), "+f"(d[2]), "+f"(d[3])
        : "r"(a[0]), "r"(a[1]), "r"(a[2]), "r"(a[3]), "r"(b[0]), "r"(b[1]));
}
__device__ __forceinline__ void cp16(void* smem, const void* gmem)
{
    unsigned sa = (unsigned)__cvta_generic_to_shared(smem);
    asm volatile("cp.async.cg.shared.global [%0], [%1], 16;\n" :: "r"(sa), "l"(gmem));
}
__device__ __forceinline__ void cpcommit() { asm volatile("cp.async.commit_group;\n" ::: "memory"); }
template<int N> __device__ __forceinline__ void cpwait() { asm volatile("cp.async.wait_group %0;\n" :: "n"(N) : "memory"); }

__global__ void __launch_bounds__(512, 1)
gemm_fused(const float* __restrict__ x,
           const float* __restrict__ gamma, const float* __restrict__ beta,
           const float* __restrict__ b2, float* __restrict__ out)
{
    extern __shared__ __half sdyn[];
    __half* Ash   = sdyn;
    __half* Bbase = sdyn + ASZ;
    __shared__ float csum[8][64], csq[8][64];

    int t = threadIdx.x;
    int w = t >> 5, lane = t & 31;
    int grp = lane >> 2, cp = lane & 3;
    int mwarp = w >> 3, nwarp = w & 7;
    int row0 = blockIdx.x * 64;

    // ---------------- prologue: r0 + LN + fp16 into Ash ---------------------
    {
        float* sWc = (float*)Bbase;            // scratch inside B region
        float* sbc = sWc + 3*CC;
        for (int i=t; i<3*CC; i+=512) sWc[i] = g_Wc[i];
        for (int i=t; i<CC;   i+=512) sbc[i] = g_bc[i];
        __syncthreads();

        #pragma unroll 1
        for (int rr=0; rr<4; ++rr) {
            int lrow = w*4 + rr;
            int m = row0 + lrow;
            float z0 = g_z[m*3+0], z1 = g_z[m*3+1], z2 = g_z[m*3+2];
            const float4* x4 = (const float4*)(x + (size_t)m*CC);
            float4* r0out = (float4*)(g_r0 + (size_t)m*CC);
            float vals[16];
            float sum = 0.f, sq = 0.f;
            #pragma unroll
            for (int i=0; i<4; ++i) {
                int f = lane + 32*i;
                float4 xv = x4[f];
                float4 w0 = ((const float4*)sWc)[f];
                float4 w1 = ((const float4*)sWc)[128+f];
                float4 w2 = ((const float4*)sWc)[256+f];
                float4 bc = ((const float4*)sbc)[f];
                float4 r;
                r.x = xv.x + z0*w0.x + z1*w1.x + z2*w2.x + bc.x;
                r.y = xv.y + z0*w0.y + z1*w1.y + z2*w2.y + bc.y;
                r.z = xv.z + z0*w0.z + z1*w1.z + z2*w2.z + bc.z;
                r.w = xv.w + z0*w0.w + z1*w1.w + z2*w2.w + bc.w;
                r0out[f] = r;
                vals[i*4+0]=r.x; vals[i*4+1]=r.y; vals[i*4+2]=r.z; vals[i*4+3]=r.w;
                sum += r.x + r.y + r.z + r.w;
                sq  += r.x*r.x + r.y*r.y + r.z*r.z + r.w*r.w;
            }
            #pragma unroll
            for (int o=16; o>0; o>>=1) {
                sum += __shfl_xor_sync(0xffffffffu, sum, o);
                sq  += __shfl_xor_sync(0xffffffffu, sq , o);
            }
            float mu   = sum * (1.f/CC);
            float var  = sq  * (1.f/CC) - mu*mu;
            float rstd = rsqrtf(var + LN_EPS);
            int par = (lrow >> 2) & 1;
            #pragma unroll
            for (int i=0; i<4; ++i) {
                int f = lane + 32*i;
                float4 g4 = ((const float4*)gamma)[f];
                float4 b4 = ((const float4*)beta )[f];
                float y0 = (vals[i*4+0]-mu)*rstd*g4.x + b4.x;
                float y1 = (vals[i*4+1]-mu)*rstd*g4.y + b4.y;
                float y2 = (vals[i*4+2]-mu)*rstd*g4.z + b4.z;
                float y3 = (vals[i*4+3]-mu)*rstd*g4.w + b4.w;
                int kc = (lane>>2) + 8*i;
                int ki = (lane&3)*4;
                int sw = (((ki>>3) ^ par) << 3) + (ki & 7);
                int off = kc*ACH + lrow*16 + sw;
                *(__half2*)(Ash+off)   = __halves2half2(__float2half_rn(y0), __float2half_rn(y1));
                *(__half2*)(Ash+off+2) = __halves2half2(__float2half_rn(y2), __float2half_rn(y3));
            }
        }
        __syncthreads();   // A ready; B scratch region free
    }

    // ---------------- main loop: 3-stage pipeline, BK=32 --------------------
    float acc[2][8][4];
    #pragma unroll
    for (int mt=0; mt<2; ++mt)
        #pragma unroll
        for (int nt=0; nt<8; ++nt)
            #pragma unroll
            for (int c=0; c<4; ++c) acc[mt][nt][c] = 0.f;

    // load one k16-chunk of B (8192 halves) into smem at dst (swizzled)
    #define LOADCH(kc_, dsth_) {                                            \
        __half* Bh_ = (dsth_);                                              \
        _Pragma("unroll")                                                   \
        for (int p_=0; p_<2; ++p_) {                                        \
            int c_ = t + p_*512;                                            \
            int n_ = c_ >> 1, gs_ = c_ & 1;                                 \
            int d_ = n_*16 + ((gs_ ^ ((n_>>2)&1)) << 3);                    \
            cp16(Bh_+d_, g_w2h + (size_t)(kc_)*8192 + c_*8);                \
        } }

    // prologue: stages 0 and 1 in flight
    LOADCH(0, Bbase);            LOADCH(1, Bbase + BCH);            cpcommit();
    LOADCH(2, Bbase + BSTG);     LOADCH(3, Bbase + BSTG + BCH);     cpcommit();

    #pragma unroll 1
    for (int it=0; it<16; ++it) {
        if (it < 15) cpwait<1>(); else cpwait<0>();
        __syncthreads();   // stage `it` data visible; stage it-1 fully consumed

        if (it < 14) {     // refill buffer (it+2)%3 (was stage it-1's buffer)
            __half* dst = Bbase + ((it+2)%3)*BSTG;
            LOADCH(2*(it+2),   dst);
            LOADCH(2*(it+2)+1, dst + BCH);
            cpcommit();
        }

        const __half* Bst = Bbase + (it%3)*BSTG;
        #pragma unroll
        for (int s=0; s<2; ++s) {
            int c = 2*it + s;
            const __half* Ah = Ash + c*ACH;
            const __half* Bh = Bst + s*BCH;

            unsigned ah[2][4];
            #pragma unroll
            for (int mt=0; mt<2; ++mt) {
                int r0r = mwarp*32 + mt*16 + grp;
                int r1r = r0r + 8;
                int p0 = ((r0r>>2)&1) << 3;
                int p1 = ((r1r>>2)&1) << 3;
                ah[mt][0] = *(const unsigned*)&Ah[r0r*16 + p0     + 2*cp];
                ah[mt][1] = *(const unsigned*)&Ah[r1r*16 + p1     + 2*cp];
                ah[mt][2] = *(const unsigned*)&Ah[r0r*16 + (8^p0) + 2*cp];
                ah[mt][3] = *(const unsigned*)&Ah[r1r*16 + (8^p1) + 2*cp];
            }
            #pragma unroll
            for (int nt=0; nt<8; ++nt) {
                int n  = nwarp*64 + nt*8 + grp;
                int pb = ((n>>2)&1) << 3;
                unsigned bh[2];
                bh[0] = *(const unsigned*)&Bh[n*16 + pb     + 2*cp];
                bh[1] = *(const unsigned*)&Bh[n*16 + (8^pb) + 2*cp];
                #pragma unroll
                for (int mt=0; mt<2; ++mt)
                    mma_fp16(acc[mt][nt], ah[mt], bh);
            }
        }
    }

    // ---------------- epilogue: +b2, +r0, LN, write out ---------------------
    float s[2][2], q[2][2];
    #pragma unroll
    for (int mt=0; mt<2; ++mt) {
        #pragma unroll
        for (int h=0; h<2; ++h) {
            int mrow = row0 + mwarp*32 + mt*16 + grp + 8*h;
            float ps = 0.f, pq = 0.f;
            #pragma unroll
            for (int nt=0; nt<8; ++nt) {
                int col = nwarp*64 + nt*8 + 2*cp;
                float2 r0v = *(const float2*)&g_r0[(size_t)mrow*CC + col];
                float2 bb  = *(const float2*)&b2[col];
                float v0 = acc[mt][nt][2*h+0] + bb.x + r0v.x;
                float v1 = acc[mt][nt][2*h+1] + bb.y + r0v.y;
                acc[mt][nt][2*h+0] = v0;
                acc[mt][nt][2*h+1] = v1;
                ps += v0 + v1;
                pq += v0*v0 + v1*v1;
            }
            s[mt][h] = ps; q[mt][h] = pq;
        }
    }
    #pragma unroll
    for (int mt=0; mt<2; ++mt)
        #pragma unroll
        for (int h=0; h<2; ++h) {
            s[mt][h] += __shfl_xor_sync(0xffffffffu, s[mt][h], 1);
            s[mt][h] += __shfl_xor_sync(0xffffffffu, s[mt][h], 2);
            q[mt][h] += __shfl_xor_sync(0xffffffffu, q[mt][h], 1);
            q[mt][h] += __shfl_xor_sync(0xffffffffu, q[mt][h], 2);
        }
    if (cp == 0) {
        #pragma unroll
        for (int mt=0; mt<2; ++mt)
            #pragma unroll
            for (int h=0; h<2; ++h) {
                int lr = mwarp*32 + mt*16 + grp + 8*h;
                csum[nwarp][lr] = s[mt][h];
                csq [nwarp][lr] = q[mt][h];
            }
    }
    __syncthreads();

    #pragma unroll
    for (int mt=0; mt<2; ++mt) {
        #pragma unroll
        for (int h=0; h<2; ++h) {
            int lr   = mwarp*32 + mt*16 + grp + 8*h;
            int mrow = row0 + lr;
            float ts = 0.f, tq = 0.f;
            #pragma unroll
            for (int ww=0; ww<8; ++ww) { ts += csum[ww][lr]; tq += csq[ww][lr]; }
            float mu   = ts * (1.f/CC);
            float var  = tq * (1.f/CC) - mu*mu;
            float rstd = rsqrtf(var + LN_EPS);
            #pragma unroll
            for (int nt=0; nt<8; ++nt) {
                int col = nwarp*64 + nt*8 + 2*cp;
                float2 gg = *(const float2*)&gamma[col];
                float2 ee = *(const float2*)&beta[col];
                float2 o;
                o.x = (acc[mt][nt][2*h+0] - mu) * rstd * gg.x + ee.x;
                o.y = (acc[mt][nt][2*h+1] - mu) * rstd * gg.y + ee.y;
                *(float2*)&out[(size_t)mrow*CC + col] = o;
            }
        }
    }
}

// ---------------------------------------------------------------------------
extern "C" void kernel_launch(void* const* d_in, const int* in_sizes, int n_in,
                              void* d_out, int out_size)
{
    const float* x     = (const float*)d_in[0];
    const float* wq    = (const float*)d_in[1];
    const float* bq    = (const float*)d_in[2];
    const float* wk    = (const float*)d_in[3];
    const float* bk    = (const float*)d_in[4];
    const float* wv    = (const float*)d_in[5];
    const float* bv    = (const float*)d_in[6];
    const float* wo    = (const float*)d_in[7];
    const float* bo    = (const float*)d_in[8];
    const float* w1    = (const float*)d_in[9];
    const float* b1    = (const float*)d_in[10];
    const float* w2    = (const float*)d_in[11];
    const float* b2    = (const float*)d_in[12];
    const float* gamma = (const float*)d_in[13];
    const float* beta  = (const float*)d_in[14];
    float* out = (float*)d_out;

    cudaFuncSetAttribute(gemm_fused, cudaFuncAttributeMaxDynamicSharedMemorySize, GEMM_SMEM);

    prep_all   <<<272, 256>>>(w2, wo, bo, w1, b1);
    qkv_kernel <<<RR/8, 256>>>(x, wq, bq, wk, bk, wv, bv);
    attn_kernel<<<BB*(SS/32), 256>>>();
    gemm_fused <<<RR/64, 512, GEMM_SMEM>>>(x, gamma, beta, b2, out);
}